// round 1
// baseline (speedup 1.0000x reference)
#include <cuda_runtime.h>
#include <math.h>

// Problem constants
#define H2 128
#define W2 128
#define NPIX (H2 * W2)        // 16384
#define BQ 2
#define TQ 6
#define CO 64                 // COUT
#define LQ 13

// ---------------------------------------------------------------------------
// Scratch (static device globals — no dynamic allocation allowed)
// ---------------------------------------------------------------------------
__device__ float g_ys [BQ * 384 * NPIX];   // stem output  (B, T*64, 128,128)  50 MB
__device__ float g_i2h[BQ * 192 * NPIX];   // i2h conv out                     25 MB
__device__ float g_h2h[BQ * 192 * NPIX];   // ret conv out                     25 MB
__device__ float g_f1 [BQ *  32 * NPIX];   // fused flow-feature conv           4 MB
__device__ float g_fl [BQ *  26 * NPIX];   // flows (u,v interleaved per l)   3.4 MB
__device__ float g_wp [BQ * 832 * NPIX];   // warped hidden (L*64 ch)         109 MB

__device__ __forceinline__ float leaky_f(float x) { return x >= 0.f ? x : 0.2f * x; }

// ---------------------------------------------------------------------------
// Stem: conv 3x3 stride 2 pad 1, in (B,6,256,256) -> out (B,384,128,128), leaky
// grid (64, 96, 2), block 256. Each thread: 1 output pixel, 4 output channels.
// ---------------------------------------------------------------------------
__global__ void stem_k(const float* __restrict__ x, const float* __restrict__ w,
                       const float* __restrict__ bias)
{
    int pix = blockIdx.x * 256 + threadIdx.x;
    int oc0 = blockIdx.y * 4;
    int b   = blockIdx.z;
    int oy = pix >> 7, ox = pix & 127;

    float a0 = bias[oc0 + 0], a1 = bias[oc0 + 1], a2 = bias[oc0 + 2], a3 = bias[oc0 + 3];

    #pragma unroll
    for (int ic = 0; ic < 6; ic++) {
        const float* xb = x + (b * 6 + ic) * 65536;
        #pragma unroll
        for (int ky = 0; ky < 3; ky++) {
            int iy = 2 * oy - 1 + ky;
            if (iy < 0 || iy > 255) continue;
            #pragma unroll
            for (int kx = 0; kx < 3; kx++) {
                int ix = 2 * ox - 1 + kx;
                if (ix < 0 || ix > 255) continue;
                float v = __ldg(&xb[iy * 256 + ix]);
                int wi = ic * 9 + ky * 3 + kx;
                a0 += v * __ldg(&w[(oc0 + 0) * 54 + wi]);
                a1 += v * __ldg(&w[(oc0 + 1) * 54 + wi]);
                a2 += v * __ldg(&w[(oc0 + 2) * 54 + wi]);
                a3 += v * __ldg(&w[(oc0 + 3) * 54 + wi]);
            }
        }
    }
    g_ys[(b * 384 + oc0 + 0) * NPIX + pix] = leaky_f(a0);
    g_ys[(b * 384 + oc0 + 1) * NPIX + pix] = leaky_f(a1);
    g_ys[(b * 384 + oc0 + 2) * NPIX + pix] = leaky_f(a2);
    g_ys[(b * 384 + oc0 + 3) * NPIX + pix] = leaky_f(a3);
}

// ---------------------------------------------------------------------------
// i2h: conv 3x3 pad 1, 64 -> 192, no activation.
// grid (64 tiles, 24 oc-groups, 2), block 256 = 32x8 pixel tile, 8 oc / thread.
// ---------------------------------------------------------------------------
__global__ void i2h_k(int t, const float* __restrict__ w, const float* __restrict__ bias)
{
    __shared__ float s_in[16][10][34];   // 16 cin chunk, tile + halo
    __shared__ float s_w [8][16][9];

    int tid = threadIdx.x;
    int tx = tid & 31, ty = tid >> 5;
    int xt0 = (blockIdx.x & 3) * 32;
    int yt0 = (blockIdx.x >> 2) * 8;
    int oc0 = blockIdx.y * 8;
    int b   = blockIdx.z;
    const float* in = g_ys + (b * 384 + t * 64) * NPIX;

    float acc[8];
    #pragma unroll
    for (int j = 0; j < 8; j++) acc[j] = bias[oc0 + j];

    for (int c0 = 0; c0 < 64; c0 += 16) {
        // weights chunk: 8 oc x 16 ic x 9
        for (int i = tid; i < 8 * 16 * 9; i += 256) {
            int j = i / 144, r = i % 144, ic = r / 9, k = r % 9;
            s_w[j][ic][k] = w[((oc0 + j) * 64 + c0 + ic) * 9 + k];
        }
        // input chunk: 16 ch x 10 x 34
        for (int i = tid; i < 16 * 340; i += 256) {
            int ic = i / 340, r = i % 340;
            int ly = r / 34, lx = r % 34;
            int gy = yt0 + ly - 1, gx = xt0 + lx - 1;
            float v = 0.f;
            if (gy >= 0 && gy < 128 && gx >= 0 && gx < 128)
                v = in[(c0 + ic) * NPIX + gy * 128 + gx];
            s_in[ic][ly][lx] = v;
        }
        __syncthreads();

        #pragma unroll 4
        for (int ic = 0; ic < 16; ic++) {
            float v[9];
            #pragma unroll
            for (int ky = 0; ky < 3; ky++)
                #pragma unroll
                for (int kx = 0; kx < 3; kx++)
                    v[ky * 3 + kx] = s_in[ic][ty + ky][tx + kx];
            #pragma unroll
            for (int j = 0; j < 8; j++) {
                float a = acc[j];
                #pragma unroll
                for (int k = 0; k < 9; k++) a += v[k] * s_w[j][ic][k];
                acc[j] = a;
            }
        }
        __syncthreads();
    }
    int pix = (yt0 + ty) * 128 + xt0 + tx;
    #pragma unroll
    for (int j = 0; j < 8; j++)
        g_i2h[(b * 192 + oc0 + j) * NPIX + pix] = acc[j];
}

// ---------------------------------------------------------------------------
// f1: leaky(conv5x5(xt, w_i2f) + conv5x5(hprev, w_h2f) + b_i2f + b_h2f), 32 out ch.
// grid (64 tiles, 4 oc-groups, 2), block 256.
// ---------------------------------------------------------------------------
__global__ void f1_k(int t, int first,
                     const float* __restrict__ wi, const float* __restrict__ bi,
                     const float* __restrict__ wh, const float* __restrict__ bh,
                     const float* __restrict__ outp)
{
    __shared__ float s_in[8][12][36];   // 8 cin chunk, 5x5 halo
    __shared__ float s_w [8][8][25];

    int tid = threadIdx.x;
    int tx = tid & 31, ty = tid >> 5;
    int xt0 = (blockIdx.x & 3) * 32;
    int yt0 = (blockIdx.x >> 2) * 8;
    int oc0 = blockIdx.y * 8;
    int b   = blockIdx.z;

    float acc[8];
    #pragma unroll
    for (int j = 0; j < 8; j++) acc[j] = bi[oc0 + j] + bh[oc0 + j];

    int nsrc = first ? 1 : 2;
    for (int src = 0; src < nsrc; src++) {
        const float* in = (src == 0) ? (g_ys + (b * 384 + t * 64) * NPIX)
                                     : (outp + ((b * 6 + (t - 1)) * 64) * NPIX);
        const float* w  = (src == 0) ? wi : wh;

        for (int c0 = 0; c0 < 64; c0 += 8) {
            for (int i = tid; i < 8 * 8 * 25; i += 256) {
                int j = i / 200, r = i % 200, ic = r / 25, k = r % 25;
                s_w[j][ic][k] = w[((oc0 + j) * 64 + c0 + ic) * 25 + k];
            }
            for (int i = tid; i < 8 * 432; i += 256) {
                int ic = i / 432, r = i % 432;
                int ly = r / 36, lx = r % 36;
                int gy = yt0 + ly - 2, gx = xt0 + lx - 2;
                float v = 0.f;
                if (gy >= 0 && gy < 128 && gx >= 0 && gx < 128)
                    v = in[(c0 + ic) * NPIX + gy * 128 + gx];
                s_in[ic][ly][lx] = v;
            }
            __syncthreads();

            for (int ic = 0; ic < 8; ic++) {
                float v[25];
                #pragma unroll
                for (int ky = 0; ky < 5; ky++)
                    #pragma unroll
                    for (int kx = 0; kx < 5; kx++)
                        v[ky * 5 + kx] = s_in[ic][ty + ky][tx + kx];
                #pragma unroll
                for (int j = 0; j < 8; j++) {
                    float a = acc[j];
                    #pragma unroll
                    for (int k = 0; k < 25; k++) a += v[k] * s_w[j][ic][k];
                    acc[j] = a;
                }
            }
            __syncthreads();
        }
    }
    int pix = (yt0 + ty) * 128 + xt0 + tx;
    #pragma unroll
    for (int j = 0; j < 8; j++)
        g_f1[(b * 32 + oc0 + j) * NPIX + pix] = leaky_f(acc[j]);
}

// ---------------------------------------------------------------------------
// flow: conv 5x5 pad 2, 32 -> 26, no activation.
// grid (64 tiles, 2 oc-groups of 13, 2), block 256.
// ---------------------------------------------------------------------------
__global__ void flow_k(const float* __restrict__ w, const float* __restrict__ bias)
{
    __shared__ float s_in[8][12][36];
    __shared__ float s_w [13][8][25];

    int tid = threadIdx.x;
    int tx = tid & 31, ty = tid >> 5;
    int xt0 = (blockIdx.x & 3) * 32;
    int yt0 = (blockIdx.x >> 2) * 8;
    int oc0 = blockIdx.y * 13;
    int b   = blockIdx.z;
    const float* in = g_f1 + b * 32 * NPIX;

    float acc[13];
    #pragma unroll
    for (int j = 0; j < 13; j++) acc[j] = bias[oc0 + j];

    for (int c0 = 0; c0 < 32; c0 += 8) {
        for (int i = tid; i < 13 * 8 * 25; i += 256) {
            int j = i / 200, r = i % 200, ic = r / 25, k = r % 25;
            s_w[j][ic][k] = w[((oc0 + j) * 32 + c0 + ic) * 25 + k];
        }
        for (int i = tid; i < 8 * 432; i += 256) {
            int ic = i / 432, r = i % 432;
            int ly = r / 36, lx = r % 36;
            int gy = yt0 + ly - 2, gx = xt0 + lx - 2;
            float v = 0.f;
            if (gy >= 0 && gy < 128 && gx >= 0 && gx < 128)
                v = in[(c0 + ic) * NPIX + gy * 128 + gx];
            s_in[ic][ly][lx] = v;
        }
        __syncthreads();

        for (int ic = 0; ic < 8; ic++) {
            float v[25];
            #pragma unroll
            for (int ky = 0; ky < 5; ky++)
                #pragma unroll
                for (int kx = 0; kx < 5; kx++)
                    v[ky * 5 + kx] = s_in[ic][ty + ky][tx + kx];
            #pragma unroll
            for (int j = 0; j < 13; j++) {
                float a = acc[j];
                #pragma unroll
                for (int k = 0; k < 25; k++) a += v[k] * s_w[j][ic][k];
                acc[j] = a;
            }
        }
        __syncthreads();
    }
    int pix = (yt0 + ty) * 128 + xt0 + tx;
    #pragma unroll
    for (int j = 0; j < 13; j++)
        g_fl[(b * 26 + oc0 + j) * NPIX + pix] = acc[j];
}

// ---------------------------------------------------------------------------
// warp: bilinear sample hprev at (x - u, y - v) for each of 13 flows x 64 ch.
// grid (64, 13, 2), block 256: 1 thread per (flow, pixel), loop 64 channels.
// 4-tap corner data computed once, shared across channels.
// ---------------------------------------------------------------------------
__global__ void warp_k(int t, const float* __restrict__ outp)
{
    int pix = blockIdx.x * 256 + threadIdx.x;
    int l   = blockIdx.y;
    int b   = blockIdx.z;

    float u = g_fl[(b * 26 + 2 * l + 0) * NPIX + pix];
    float v = g_fl[(b * 26 + 2 * l + 1) * NPIX + pix];
    float sx = (float)(pix & 127) - u;
    float sy = (float)(pix >> 7)  - v;

    float fx = floorf(sx), fy = floorf(sy);
    float wx1 = sx - fx, wx0 = 1.f - wx1;
    float wy1 = sy - fy, wy0 = 1.f - wy1;
    int x0 = (int)fx, y0 = (int)fy;
    int x1 = x0 + 1,  y1 = y0 + 1;

    bool vx0 = (x0 >= 0) & (x0 <= 127);
    bool vx1 = (x1 >= 0) & (x1 <= 127);
    bool vy0 = (y0 >= 0) & (y0 <= 127);
    bool vy1 = (y1 >= 0) & (y1 <= 127);

    int cx0 = min(max(x0, 0), 127), cx1 = min(max(x1, 0), 127);
    int cy0 = min(max(y0, 0), 127), cy1 = min(max(y1, 0), 127);

    int i00 = cy0 * 128 + cx0, i10 = cy0 * 128 + cx1;
    int i01 = cy1 * 128 + cx0, i11 = cy1 * 128 + cx1;

    float w00 = (vx0 && vy0) ? wx0 * wy0 : 0.f;
    float w10 = (vx1 && vy0) ? wx1 * wy0 : 0.f;
    float w01 = (vx0 && vy1) ? wx0 * wy1 : 0.f;
    float w11 = (vx1 && vy1) ? wx1 * wy1 : 0.f;

    const float* hp = outp + ((b * 6 + (t - 1)) * 64) * NPIX;
    float* wp = g_wp + ((b * 13 + l) * 64) * NPIX + pix;

    #pragma unroll 4
    for (int c = 0; c < 64; c++) {
        const float* hc = hp + c * NPIX;
        float val = w00 * __ldg(&hc[i00]) + w10 * __ldg(&hc[i10])
                  + w01 * __ldg(&hc[i01]) + w11 * __ldg(&hc[i11]);
        wp[c * NPIX] = val;
    }
}

// ---------------------------------------------------------------------------
// ret: 1x1 conv == SGEMM  C[192, 16384] = W[192,832] * X[832, 16384] + bias,
// per batch. BM=64, BN=64, BK=16, 256 threads, 4x4 microtile.
// grid (256, 3, 2). first => warped==0 => output = bias only.
// ---------------------------------------------------------------------------
__global__ void ret_k(const float* __restrict__ W, const float* __restrict__ bias, int first)
{
    __shared__ float As[64][17];
    __shared__ float Bs[16][64];

    int tid = threadIdx.x;
    int b   = blockIdx.z;
    int n0  = blockIdx.x * 64;
    int m0  = blockIdx.y * 64;
    int tn = tid & 15, tm = tid >> 4;

    const float* X = g_wp + b * 832 * NPIX;
    float acc[4][4];
    #pragma unroll
    for (int i = 0; i < 4; i++)
        #pragma unroll
        for (int j = 0; j < 4; j++) acc[i][j] = 0.f;

    int nk = first ? 0 : 52;
    for (int kt = 0; kt < nk; kt++) {
        int k0 = kt * 16;
        #pragma unroll
        for (int j = 0; j < 4; j++) {
            int i = tid + j * 256;
            int m = i >> 4, k = i & 15;
            As[m][k] = W[(m0 + m) * 832 + k0 + k];
            int kb = i >> 6, n = i & 63;
            Bs[kb][n] = X[(k0 + kb) * NPIX + n0 + n];
        }
        __syncthreads();
        #pragma unroll
        for (int kk = 0; kk < 16; kk++) {
            float4 bv = *reinterpret_cast<const float4*>(&Bs[kk][tn * 4]);
            float a0 = As[tm * 4 + 0][kk];
            float a1 = As[tm * 4 + 1][kk];
            float a2 = As[tm * 4 + 2][kk];
            float a3 = As[tm * 4 + 3][kk];
            acc[0][0] += a0 * bv.x; acc[0][1] += a0 * bv.y; acc[0][2] += a0 * bv.z; acc[0][3] += a0 * bv.w;
            acc[1][0] += a1 * bv.x; acc[1][1] += a1 * bv.y; acc[1][2] += a1 * bv.z; acc[1][3] += a1 * bv.w;
            acc[2][0] += a2 * bv.x; acc[2][1] += a2 * bv.y; acc[2][2] += a2 * bv.z; acc[2][3] += a2 * bv.w;
            acc[3][0] += a3 * bv.x; acc[3][1] += a3 * bv.y; acc[3][2] += a3 * bv.z; acc[3][3] += a3 * bv.w;
        }
        __syncthreads();
    }

    float* C = g_h2h + b * 192 * NPIX;
    #pragma unroll
    for (int i = 0; i < 4; i++) {
        int m = m0 + tm * 4 + i;
        float bb = bias[m];
        float4 o = make_float4(acc[i][0] + bb, acc[i][1] + bb, acc[i][2] + bb, acc[i][3] + bb);
        *reinterpret_cast<float4*>(&C[m * NPIX + n0 + tn * 4]) = o;
    }
}

// ---------------------------------------------------------------------------
// GRU elementwise update; writes out[b, t] directly.
// grid (64, 64, 2), block 256.
// ---------------------------------------------------------------------------
__global__ void gru_k(int t, int first, float* __restrict__ outp)
{
    int pix = blockIdx.x * 256 + threadIdx.x;
    int c   = blockIdx.y;
    int b   = blockIdx.z;
    int base = b * 192 * NPIX;

    float ir = g_i2h[base + (c      ) * NPIX + pix];
    float iu = g_i2h[base + (c +  64) * NPIX + pix];
    float im = g_i2h[base + (c + 128) * NPIX + pix];
    float hr = g_h2h[base + (c      ) * NPIX + pix];
    float hu = g_h2h[base + (c +  64) * NPIX + pix];
    float hm = g_h2h[base + (c + 128) * NPIX + pix];

    float r = 1.f / (1.f + expf(-(ir + hr)));
    float z = 1.f / (1.f + expf(-(iu + hu)));
    float m = leaky_f(im + r * hm);

    float hp = first ? 0.f : outp[((b * 6 + t - 1) * 64 + c) * NPIX + pix];
    outp[((b * 6 + t) * 64 + c) * NPIX + pix] = z * hp + (1.f - z) * m;
}

// ---------------------------------------------------------------------------
// Launch
// ---------------------------------------------------------------------------
extern "C" void kernel_launch(void* const* d_in, const int* in_sizes, int n_in,
                              void* d_out, int out_size)
{
    const float* x      = (const float*)d_in[0];
    const float* w_stem = (const float*)d_in[1];
    const float* b_stem = (const float*)d_in[2];
    const float* w_i2h  = (const float*)d_in[3];
    const float* b_i2h  = (const float*)d_in[4];
    const float* w_i2f  = (const float*)d_in[5];
    const float* b_i2f  = (const float*)d_in[6];
    const float* w_h2f  = (const float*)d_in[7];
    const float* b_h2f  = (const float*)d_in[8];
    const float* w_flow = (const float*)d_in[9];
    const float* b_flow = (const float*)d_in[10];
    const float* w_ret  = (const float*)d_in[11];
    const float* b_ret  = (const float*)d_in[12];
    float* outp = (float*)d_out;

    stem_k<<<dim3(64, 96, 2), 256>>>(x, w_stem, b_stem);

    for (int t = 0; t < 6; t++) {
        int first = (t == 0) ? 1 : 0;
        i2h_k <<<dim3(64, 24, 2), 256>>>(t, w_i2h, b_i2h);
        f1_k  <<<dim3(64,  4, 2), 256>>>(t, first, w_i2f, b_i2f, w_h2f, b_h2f, outp);
        flow_k<<<dim3(64,  2, 2), 256>>>(w_flow, b_flow);
        if (!first)
            warp_k<<<dim3(64, 13, 2), 256>>>(t, outp);
        ret_k <<<dim3(256, 3, 2), 256>>>(w_ret, b_ret, first);
        gru_k <<<dim3(64, 64, 2), 256>>>(t, first, outp);
    }
}

// round 2
// speedup vs baseline: 1.0012x; 1.0012x over previous
#include <cuda_runtime.h>
#include <math.h>

// Problem constants
#define H2 128
#define W2 128
#define NPIX (H2 * W2)        // 16384
#define BQ 2
#define TQ 6
#define CO 64                 // COUT
#define LQ 13

// ---------------------------------------------------------------------------
// Scratch (static device globals — no dynamic allocation allowed)
// ---------------------------------------------------------------------------
__device__ float g_ys [BQ * 384 * NPIX];   // stem output  (B, T*64, 128,128)  50 MB
__device__ float g_i2h[BQ * 192 * NPIX];   // i2h conv out                     25 MB
__device__ float g_h2h[BQ * 192 * NPIX];   // ret conv out                     25 MB
__device__ float g_f1 [BQ *  32 * NPIX];   // fused flow-feature conv           4 MB
__device__ float g_fl [BQ *  26 * NPIX];   // flows (u,v interleaved per l)   3.4 MB
__device__ float g_wp [BQ * 832 * NPIX];   // warped hidden (L*64 ch)         109 MB

__device__ __forceinline__ float leaky_f(float x) { return x >= 0.f ? x : 0.2f * x; }

// ---------------------------------------------------------------------------
// Stem: conv 3x3 stride 2 pad 1, in (B,6,256,256) -> out (B,384,128,128), leaky
// grid (64, 96, 2), block 256. Each thread: 1 output pixel, 4 output channels.
// ---------------------------------------------------------------------------
__global__ void stem_k(const float* __restrict__ x, const float* __restrict__ w,
                       const float* __restrict__ bias)
{
    int pix = blockIdx.x * 256 + threadIdx.x;
    int oc0 = blockIdx.y * 4;
    int b   = blockIdx.z;
    int oy = pix >> 7, ox = pix & 127;

    float a0 = bias[oc0 + 0], a1 = bias[oc0 + 1], a2 = bias[oc0 + 2], a3 = bias[oc0 + 3];

    #pragma unroll
    for (int ic = 0; ic < 6; ic++) {
        const float* xb = x + (b * 6 + ic) * 65536;
        #pragma unroll
        for (int ky = 0; ky < 3; ky++) {
            int iy = 2 * oy - 1 + ky;
            if (iy < 0 || iy > 255) continue;
            #pragma unroll
            for (int kx = 0; kx < 3; kx++) {
                int ix = 2 * ox - 1 + kx;
                if (ix < 0 || ix > 255) continue;
                float v = __ldg(&xb[iy * 256 + ix]);
                int wi = ic * 9 + ky * 3 + kx;
                a0 += v * __ldg(&w[(oc0 + 0) * 54 + wi]);
                a1 += v * __ldg(&w[(oc0 + 1) * 54 + wi]);
                a2 += v * __ldg(&w[(oc0 + 2) * 54 + wi]);
                a3 += v * __ldg(&w[(oc0 + 3) * 54 + wi]);
            }
        }
    }
    g_ys[(b * 384 + oc0 + 0) * NPIX + pix] = leaky_f(a0);
    g_ys[(b * 384 + oc0 + 1) * NPIX + pix] = leaky_f(a1);
    g_ys[(b * 384 + oc0 + 2) * NPIX + pix] = leaky_f(a2);
    g_ys[(b * 384 + oc0 + 3) * NPIX + pix] = leaky_f(a3);
}

// ---------------------------------------------------------------------------
// i2h: conv 3x3 pad 1, 64 -> 192, no activation.
// grid (64 tiles, 24 oc-groups, 2), block 256 = 32x8 pixel tile, 8 oc / thread.
// ---------------------------------------------------------------------------
__global__ void i2h_k(int t, const float* __restrict__ w, const float* __restrict__ bias)
{
    __shared__ float s_in[16][10][34];   // 16 cin chunk, tile + halo
    __shared__ float s_w [8][16][9];

    int tid = threadIdx.x;
    int tx = tid & 31, ty = tid >> 5;
    int xt0 = (blockIdx.x & 3) * 32;
    int yt0 = (blockIdx.x >> 2) * 8;
    int oc0 = blockIdx.y * 8;
    int b   = blockIdx.z;
    const float* in = g_ys + (b * 384 + t * 64) * NPIX;

    float acc[8];
    #pragma unroll
    for (int j = 0; j < 8; j++) acc[j] = bias[oc0 + j];

    for (int c0 = 0; c0 < 64; c0 += 16) {
        // weights chunk: 8 oc x 16 ic x 9
        for (int i = tid; i < 8 * 16 * 9; i += 256) {
            int j = i / 144, r = i % 144, ic = r / 9, k = r % 9;
            s_w[j][ic][k] = w[((oc0 + j) * 64 + c0 + ic) * 9 + k];
        }
        // input chunk: 16 ch x 10 x 34
        for (int i = tid; i < 16 * 340; i += 256) {
            int ic = i / 340, r = i % 340;
            int ly = r / 34, lx = r % 34;
            int gy = yt0 + ly - 1, gx = xt0 + lx - 1;
            float v = 0.f;
            if (gy >= 0 && gy < 128 && gx >= 0 && gx < 128)
                v = in[(c0 + ic) * NPIX + gy * 128 + gx];
            s_in[ic][ly][lx] = v;
        }
        __syncthreads();

        #pragma unroll 4
        for (int ic = 0; ic < 16; ic++) {
            float v[9];
            #pragma unroll
            for (int ky = 0; ky < 3; ky++)
                #pragma unroll
                for (int kx = 0; kx < 3; kx++)
                    v[ky * 3 + kx] = s_in[ic][ty + ky][tx + kx];
            #pragma unroll
            for (int j = 0; j < 8; j++) {
                float a = acc[j];
                #pragma unroll
                for (int k = 0; k < 9; k++) a += v[k] * s_w[j][ic][k];
                acc[j] = a;
            }
        }
        __syncthreads();
    }
    int pix = (yt0 + ty) * 128 + xt0 + tx;
    #pragma unroll
    for (int j = 0; j < 8; j++)
        g_i2h[(b * 192 + oc0 + j) * NPIX + pix] = acc[j];
}

// ---------------------------------------------------------------------------
// f1: leaky(conv5x5(xt, w_i2f) + conv5x5(hprev, w_h2f) + b_i2f + b_h2f), 32 out ch.
// grid (64 tiles, 4 oc-groups, 2), block 256.
// ---------------------------------------------------------------------------
__global__ void f1_k(int t, int first,
                     const float* __restrict__ wi, const float* __restrict__ bi,
                     const float* __restrict__ wh, const float* __restrict__ bh,
                     const float* __restrict__ outp)
{
    __shared__ float s_in[8][12][36];   // 8 cin chunk, 5x5 halo
    __shared__ float s_w [8][8][25];

    int tid = threadIdx.x;
    int tx = tid & 31, ty = tid >> 5;
    int xt0 = (blockIdx.x & 3) * 32;
    int yt0 = (blockIdx.x >> 2) * 8;
    int oc0 = blockIdx.y * 8;
    int b   = blockIdx.z;

    float acc[8];
    #pragma unroll
    for (int j = 0; j < 8; j++) acc[j] = bi[oc0 + j] + bh[oc0 + j];

    int nsrc = first ? 1 : 2;
    for (int src = 0; src < nsrc; src++) {
        const float* in = (src == 0) ? (g_ys + (b * 384 + t * 64) * NPIX)
                                     : (outp + ((b * 6 + (t - 1)) * 64) * NPIX);
        const float* w  = (src == 0) ? wi : wh;

        for (int c0 = 0; c0 < 64; c0 += 8) {
            for (int i = tid; i < 8 * 8 * 25; i += 256) {
                int j = i / 200, r = i % 200, ic = r / 25, k = r % 25;
                s_w[j][ic][k] = w[((oc0 + j) * 64 + c0 + ic) * 25 + k];
            }
            for (int i = tid; i < 8 * 432; i += 256) {
                int ic = i / 432, r = i % 432;
                int ly = r / 36, lx = r % 36;
                int gy = yt0 + ly - 2, gx = xt0 + lx - 2;
                float v = 0.f;
                if (gy >= 0 && gy < 128 && gx >= 0 && gx < 128)
                    v = in[(c0 + ic) * NPIX + gy * 128 + gx];
                s_in[ic][ly][lx] = v;
            }
            __syncthreads();

            for (int ic = 0; ic < 8; ic++) {
                float v[25];
                #pragma unroll
                for (int ky = 0; ky < 5; ky++)
                    #pragma unroll
                    for (int kx = 0; kx < 5; kx++)
                        v[ky * 5 + kx] = s_in[ic][ty + ky][tx + kx];
                #pragma unroll
                for (int j = 0; j < 8; j++) {
                    float a = acc[j];
                    #pragma unroll
                    for (int k = 0; k < 25; k++) a += v[k] * s_w[j][ic][k];
                    acc[j] = a;
                }
            }
            __syncthreads();
        }
    }
    int pix = (yt0 + ty) * 128 + xt0 + tx;
    #pragma unroll
    for (int j = 0; j < 8; j++)
        g_f1[(b * 32 + oc0 + j) * NPIX + pix] = leaky_f(acc[j]);
}

// ---------------------------------------------------------------------------
// flow: conv 5x5 pad 2, 32 -> 26, no activation.
// grid (64 tiles, 2 oc-groups of 13, 2), block 256.
// ---------------------------------------------------------------------------
__global__ void flow_k(const float* __restrict__ w, const float* __restrict__ bias)
{
    __shared__ float s_in[8][12][36];
    __shared__ float s_w [13][8][25];

    int tid = threadIdx.x;
    int tx = tid & 31, ty = tid >> 5;
    int xt0 = (blockIdx.x & 3) * 32;
    int yt0 = (blockIdx.x >> 2) * 8;
    int oc0 = blockIdx.y * 13;
    int b   = blockIdx.z;
    const float* in = g_f1 + b * 32 * NPIX;

    float acc[13];
    #pragma unroll
    for (int j = 0; j < 13; j++) acc[j] = bias[oc0 + j];

    for (int c0 = 0; c0 < 32; c0 += 8) {
        for (int i = tid; i < 13 * 8 * 25; i += 256) {
            int j = i / 200, r = i % 200, ic = r / 25, k = r % 25;
            s_w[j][ic][k] = w[((oc0 + j) * 32 + c0 + ic) * 25 + k];
        }
        for (int i = tid; i < 8 * 432; i += 256) {
            int ic = i / 432, r = i % 432;
            int ly = r / 36, lx = r % 36;
            int gy = yt0 + ly - 2, gx = xt0 + lx - 2;
            float v = 0.f;
            if (gy >= 0 && gy < 128 && gx >= 0 && gx < 128)
                v = in[(c0 + ic) * NPIX + gy * 128 + gx];
            s_in[ic][ly][lx] = v;
        }
        __syncthreads();

        for (int ic = 0; ic < 8; ic++) {
            float v[25];
            #pragma unroll
            for (int ky = 0; ky < 5; ky++)
                #pragma unroll
                for (int kx = 0; kx < 5; kx++)
                    v[ky * 5 + kx] = s_in[ic][ty + ky][tx + kx];
            #pragma unroll
            for (int j = 0; j < 13; j++) {
                float a = acc[j];
                #pragma unroll
                for (int k = 0; k < 25; k++) a += v[k] * s_w[j][ic][k];
                acc[j] = a;
            }
        }
        __syncthreads();
    }
    int pix = (yt0 + ty) * 128 + xt0 + tx;
    #pragma unroll
    for (int j = 0; j < 13; j++)
        g_fl[(b * 26 + oc0 + j) * NPIX + pix] = acc[j];
}

// ---------------------------------------------------------------------------
// warp: bilinear sample hprev at (x - u, y - v) for each of 13 flows x 64 ch.
// grid (64, 13, 2), block 256: 1 thread per (flow, pixel), loop 64 channels.
// 4-tap corner data computed once, shared across channels.
// ---------------------------------------------------------------------------
__global__ void warp_k(int t, const float* __restrict__ outp)
{
    int pix = blockIdx.x * 256 + threadIdx.x;
    int l   = blockIdx.y;
    int b   = blockIdx.z;

    float u = g_fl[(b * 26 + 2 * l + 0) * NPIX + pix];
    float v = g_fl[(b * 26 + 2 * l + 1) * NPIX + pix];
    float sx = (float)(pix & 127) - u;
    float sy = (float)(pix >> 7)  - v;

    float fx = floorf(sx), fy = floorf(sy);
    float wx1 = sx - fx, wx0 = 1.f - wx1;
    float wy1 = sy - fy, wy0 = 1.f - wy1;
    int x0 = (int)fx, y0 = (int)fy;
    int x1 = x0 + 1,  y1 = y0 + 1;

    bool vx0 = (x0 >= 0) & (x0 <= 127);
    bool vx1 = (x1 >= 0) & (x1 <= 127);
    bool vy0 = (y0 >= 0) & (y0 <= 127);
    bool vy1 = (y1 >= 0) & (y1 <= 127);

    int cx0 = min(max(x0, 0), 127), cx1 = min(max(x1, 0), 127);
    int cy0 = min(max(y0, 0), 127), cy1 = min(max(y1, 0), 127);

    int i00 = cy0 * 128 + cx0, i10 = cy0 * 128 + cx1;
    int i01 = cy1 * 128 + cx0, i11 = cy1 * 128 + cx1;

    float w00 = (vx0 && vy0) ? wx0 * wy0 : 0.f;
    float w10 = (vx1 && vy0) ? wx1 * wy0 : 0.f;
    float w01 = (vx0 && vy1) ? wx0 * wy1 : 0.f;
    float w11 = (vx1 && vy1) ? wx1 * wy1 : 0.f;

    const float* hp = outp + ((b * 6 + (t - 1)) * 64) * NPIX;
    float* wp = g_wp + ((b * 13 + l) * 64) * NPIX + pix;

    #pragma unroll 4
    for (int c = 0; c < 64; c++) {
        const float* hc = hp + c * NPIX;
        float val = w00 * __ldg(&hc[i00]) + w10 * __ldg(&hc[i10])
                  + w01 * __ldg(&hc[i01]) + w11 * __ldg(&hc[i11]);
        wp[c * NPIX] = val;
    }
}

// ---------------------------------------------------------------------------
// ret: 1x1 conv == SGEMM  C[192, 16384] = W[192,832] * X[832, 16384] + bias,
// per batch. BM=64, BN=64, BK=16, 256 threads, 4x4 microtile.
// grid (256, 3, 2). first => warped==0 => output = bias only.
// ---------------------------------------------------------------------------
__global__ void ret_k(const float* __restrict__ W, const float* __restrict__ bias, int first)
{
    __shared__ float As[64][17];
    __shared__ float Bs[16][64];

    int tid = threadIdx.x;
    int b   = blockIdx.z;
    int n0  = blockIdx.x * 64;
    int m0  = blockIdx.y * 64;
    int tn = tid & 15, tm = tid >> 4;

    const float* X = g_wp + b * 832 * NPIX;
    float acc[4][4];
    #pragma unroll
    for (int i = 0; i < 4; i++)
        #pragma unroll
        for (int j = 0; j < 4; j++) acc[i][j] = 0.f;

    int nk = first ? 0 : 52;
    for (int kt = 0; kt < nk; kt++) {
        int k0 = kt * 16;
        #pragma unroll
        for (int j = 0; j < 4; j++) {
            int i = tid + j * 256;
            int m = i >> 4, k = i & 15;
            As[m][k] = W[(m0 + m) * 832 + k0 + k];
            int kb = i >> 6, n = i & 63;
            Bs[kb][n] = X[(k0 + kb) * NPIX + n0 + n];
        }
        __syncthreads();
        #pragma unroll
        for (int kk = 0; kk < 16; kk++) {
            float4 bv = *reinterpret_cast<const float4*>(&Bs[kk][tn * 4]);
            float a0 = As[tm * 4 + 0][kk];
            float a1 = As[tm * 4 + 1][kk];
            float a2 = As[tm * 4 + 2][kk];
            float a3 = As[tm * 4 + 3][kk];
            acc[0][0] += a0 * bv.x; acc[0][1] += a0 * bv.y; acc[0][2] += a0 * bv.z; acc[0][3] += a0 * bv.w;
            acc[1][0] += a1 * bv.x; acc[1][1] += a1 * bv.y; acc[1][2] += a1 * bv.z; acc[1][3] += a1 * bv.w;
            acc[2][0] += a2 * bv.x; acc[2][1] += a2 * bv.y; acc[2][2] += a2 * bv.z; acc[2][3] += a2 * bv.w;
            acc[3][0] += a3 * bv.x; acc[3][1] += a3 * bv.y; acc[3][2] += a3 * bv.z; acc[3][3] += a3 * bv.w;
        }
        __syncthreads();
    }

    float* C = g_h2h + b * 192 * NPIX;
    #pragma unroll
    for (int i = 0; i < 4; i++) {
        int m = m0 + tm * 4 + i;
        float bb = bias[m];
        float4 o = make_float4(acc[i][0] + bb, acc[i][1] + bb, acc[i][2] + bb, acc[i][3] + bb);
        *reinterpret_cast<float4*>(&C[m * NPIX + n0 + tn * 4]) = o;
    }
}

// ---------------------------------------------------------------------------
// GRU elementwise update; writes out[b, t] directly.
// grid (64, 64, 2), block 256.
// ---------------------------------------------------------------------------
__global__ void gru_k(int t, int first, float* __restrict__ outp)
{
    int pix = blockIdx.x * 256 + threadIdx.x;
    int c   = blockIdx.y;
    int b   = blockIdx.z;
    int base = b * 192 * NPIX;

    float ir = g_i2h[base + (c      ) * NPIX + pix];
    float iu = g_i2h[base + (c +  64) * NPIX + pix];
    float im = g_i2h[base + (c + 128) * NPIX + pix];
    float hr = g_h2h[base + (c      ) * NPIX + pix];
    float hu = g_h2h[base + (c +  64) * NPIX + pix];
    float hm = g_h2h[base + (c + 128) * NPIX + pix];

    float r = 1.f / (1.f + expf(-(ir + hr)));
    float z = 1.f / (1.f + expf(-(iu + hu)));
    float m = leaky_f(im + r * hm);

    float hp = first ? 0.f : outp[((b * 6 + t - 1) * 64 + c) * NPIX + pix];
    outp[((b * 6 + t) * 64 + c) * NPIX + pix] = z * hp + (1.f - z) * m;
}

// ---------------------------------------------------------------------------
// Launch
// ---------------------------------------------------------------------------
extern "C" void kernel_launch(void* const* d_in, const int* in_sizes, int n_in,
                              void* d_out, int out_size)
{
    const float* x      = (const float*)d_in[0];
    const float* w_stem = (const float*)d_in[1];
    const float* b_stem = (const float*)d_in[2];
    const float* w_i2h  = (const float*)d_in[3];
    const float* b_i2h  = (const float*)d_in[4];
    const float* w_i2f  = (const float*)d_in[5];
    const float* b_i2f  = (const float*)d_in[6];
    const float* w_h2f  = (const float*)d_in[7];
    const float* b_h2f  = (const float*)d_in[8];
    const float* w_flow = (const float*)d_in[9];
    const float* b_flow = (const float*)d_in[10];
    const float* w_ret  = (const float*)d_in[11];
    const float* b_ret  = (const float*)d_in[12];
    float* outp = (float*)d_out;

    stem_k<<<dim3(64, 96, 2), 256>>>(x, w_stem, b_stem);

    for (int t = 0; t < 6; t++) {
        int first = (t == 0) ? 1 : 0;
        i2h_k <<<dim3(64, 24, 2), 256>>>(t, w_i2h, b_i2h);
        f1_k  <<<dim3(64,  4, 2), 256>>>(t, first, w_i2f, b_i2f, w_h2f, b_h2f, outp);
        flow_k<<<dim3(64,  2, 2), 256>>>(w_flow, b_flow);
        if (!first)
            warp_k<<<dim3(64, 13, 2), 256>>>(t, outp);
        ret_k <<<dim3(256, 3, 2), 256>>>(w_ret, b_ret, first);
        gru_k <<<dim3(64, 64, 2), 256>>>(t, first, outp);
    }
}

// round 3
// speedup vs baseline: 1.3422x; 1.3406x over previous
#include <cuda_runtime.h>
#include <math.h>

#define NPIX 16384            // 128*128
#define H2 128
#define W2 128

// ---------------------------------------------------------------------------
// Scratch (static device globals)
// ---------------------------------------------------------------------------
__device__ float g_ys [2 * 384 * NPIX];     // stem output               50 MB
__device__ float g_i2h[2 * 192 * NPIX];     // i2h conv out              25 MB
__device__ float g_h2h[2 * 192 * NPIX];     // ret conv out              25 MB
__device__ float g_f1 [2 *  32 * NPIX];     // combined flow features     4 MB
__device__ float g_f1p[4][2 * 32 * NPIX];   // f1 partial sums           17 MB
__device__ float g_fl [2 *  26 * NPIX];     // flows                    3.4 MB
__device__ float g_flp[2][2 * 32 * NPIX];   // flow partial sums        8.4 MB
__device__ float g_wp [2 * 832 * NPIX];     // warped hidden            109 MB

__device__ __forceinline__ float leaky_f(float x) { return x >= 0.f ? x : 0.2f * x; }

// ---------------------------------------------------------------------------
// Stem: conv 3x3 stride 2 pad 1, (B,6,256,256) -> (B,384,128,128), leaky
// ---------------------------------------------------------------------------
__global__ void stem_k(const float* __restrict__ x, const float* __restrict__ w,
                       const float* __restrict__ bias)
{
    int pix = blockIdx.x * 256 + threadIdx.x;
    int oc0 = blockIdx.y * 4;
    int b   = blockIdx.z;
    int oy = pix >> 7, ox = pix & 127;

    float a0 = bias[oc0 + 0], a1 = bias[oc0 + 1], a2 = bias[oc0 + 2], a3 = bias[oc0 + 3];

    #pragma unroll
    for (int ic = 0; ic < 6; ic++) {
        const float* xb = x + (b * 6 + ic) * 65536;
        #pragma unroll
        for (int ky = 0; ky < 3; ky++) {
            int iy = 2 * oy - 1 + ky;
            if (iy < 0 || iy > 255) continue;
            #pragma unroll
            for (int kx = 0; kx < 3; kx++) {
                int ix = 2 * ox - 1 + kx;
                if (ix < 0 || ix > 255) continue;
                float v = __ldg(&xb[iy * 256 + ix]);
                int wi = ic * 9 + ky * 3 + kx;
                a0 += v * __ldg(&w[(oc0 + 0) * 54 + wi]);
                a1 += v * __ldg(&w[(oc0 + 1) * 54 + wi]);
                a2 += v * __ldg(&w[(oc0 + 2) * 54 + wi]);
                a3 += v * __ldg(&w[(oc0 + 3) * 54 + wi]);
            }
        }
    }
    g_ys[(b * 384 + oc0 + 0) * NPIX + pix] = leaky_f(a0);
    g_ys[(b * 384 + oc0 + 1) * NPIX + pix] = leaky_f(a1);
    g_ys[(b * 384 + oc0 + 2) * NPIX + pix] = leaky_f(a2);
    g_ys[(b * 384 + oc0 + 3) * NPIX + pix] = leaky_f(a3);
}

// ---------------------------------------------------------------------------
// i2h: conv 3x3 pad 1, 64 -> 192.
// Tile 32x64 pixels, 256 threads, each: 8 oc x 8 x-pixels (64 acc).
// Weights transposed in smem [ic][k][oc8] -> vector broadcast loads.
// grid (8, 24, 2)
// ---------------------------------------------------------------------------
__global__ __launch_bounds__(256) void i2h_k(int t, const float* __restrict__ w,
                                             const float* __restrict__ bias)
{
    __shared__ __align__(16) float s_in[4][66][36];
    __shared__ __align__(16) float s_w [4][9][8];

    int tid = threadIdx.x;
    int tx = tid & 3, ty = tid >> 2;           // tx: x-group of 8, ty: row
    int xt0 = (blockIdx.x & 3) * 32;
    int yt0 = (blockIdx.x >> 2) * 64;
    int oc0 = blockIdx.y * 8;
    int b   = blockIdx.z;
    const float* in = g_ys + (b * 384 + t * 64) * NPIX;

    float acc[8][8];
    #pragma unroll
    for (int j = 0; j < 8; j++) {
        float bv = bias[oc0 + j];
        #pragma unroll
        for (int p = 0; p < 8; p++) acc[j][p] = bv;
    }

    for (int c0 = 0; c0 < 64; c0 += 4) {
        for (int i = tid; i < 288; i += 256) {
            int ic = i / 72, r = i % 72, k = r >> 3, j = r & 7;
            s_w[ic][k][j] = w[((oc0 + j) * 64 + c0 + ic) * 9 + k];
        }
        for (int i = tid; i < 4 * 66 * 36; i += 256) {
            int ic = i / 2376, r = i % 2376, ly = r / 36, lx = r % 36;
            int gy = yt0 + ly - 1, gx = xt0 + lx - 1;
            float v = 0.f;
            if (lx < 34 && gy >= 0 && gy < 128 && gx >= 0 && gx < 128)
                v = in[(c0 + ic) * NPIX + gy * 128 + gx];
            s_in[ic][ly][lx] = v;
        }
        __syncthreads();

        #pragma unroll 1
        for (int ic = 0; ic < 4; ic++) {
            #pragma unroll
            for (int ky = 0; ky < 3; ky++) {
                float bb[12];
                *(float4*)&bb[0] = *(const float4*)&s_in[ic][ty + ky][tx * 8];
                *(float4*)&bb[4] = *(const float4*)&s_in[ic][ty + ky][tx * 8 + 4];
                *(float4*)&bb[8] = *(const float4*)&s_in[ic][ty + ky][tx * 8 + 8];
                #pragma unroll
                for (int kx = 0; kx < 3; kx++) {
                    float a[8];
                    *(float4*)&a[0] = *(const float4*)&s_w[ic][ky * 3 + kx][0];
                    *(float4*)&a[4] = *(const float4*)&s_w[ic][ky * 3 + kx][4];
                    #pragma unroll
                    for (int j = 0; j < 8; j++)
                        #pragma unroll
                        for (int p = 0; p < 8; p++)
                            acc[j][p] += a[j] * bb[kx + p];
                }
            }
        }
        __syncthreads();
    }

    int pix = (yt0 + ty) * 128 + xt0 + tx * 8;
    #pragma unroll
    for (int j = 0; j < 8; j++) {
        float* o = &g_i2h[(b * 192 + oc0 + j) * NPIX + pix];
        *(float4*)&o[0] = *(float4*)&acc[j][0];
        *(float4*)&o[4] = *(float4*)&acc[j][4];
    }
}

// ---------------------------------------------------------------------------
// f1: conv5x5(xt) + conv5x5(hprev), computed as 4 partial sums (2 src x 2
// channel halves) into g_f1p[csplit]. No bias/activation here (see f1comb).
// grid (8, 16, 2): blockIdx.y = csplit*4 + ocg
// ---------------------------------------------------------------------------
__global__ __launch_bounds__(256) void f1_k(int t, int first,
                                            const float* __restrict__ wi,
                                            const float* __restrict__ wh,
                                            const float* __restrict__ outp)
{
    __shared__ __align__(16) float s_in[4][68][40];
    __shared__ __align__(16) float s_w [4][25][8];

    int csplit = blockIdx.y >> 2;
    int src    = csplit >> 1;
    if (first && src) return;                  // hprev == 0 at t=0
    int oc0   = (blockIdx.y & 3) * 8;
    int cbase = (csplit & 1) * 32;

    int tid = threadIdx.x;
    int tx = tid & 3, ty = tid >> 2;
    int xt0 = (blockIdx.x & 3) * 32;
    int yt0 = (blockIdx.x >> 2) * 64;
    int b   = blockIdx.z;

    const float* in = src ? (outp + ((b * 6 + (t - 1)) * 64 + cbase) * NPIX)
                          : (g_ys + (b * 384 + t * 64 + cbase) * NPIX);
    const float* w  = src ? wh : wi;

    float acc[8][8];
    #pragma unroll
    for (int j = 0; j < 8; j++)
        #pragma unroll
        for (int p = 0; p < 8; p++) acc[j][p] = 0.f;

    for (int c0 = 0; c0 < 32; c0 += 4) {
        for (int i = tid; i < 800; i += 256) {
            int ic = i / 200, r = i % 200, k = r >> 3, j = r & 7;
            s_w[ic][k][j] = w[((oc0 + j) * 64 + cbase + c0 + ic) * 25 + k];
        }
        for (int i = tid; i < 4 * 68 * 40; i += 256) {
            int ic = i / 2720, r = i % 2720, ly = r / 40, lx = r % 40;
            int gy = yt0 + ly - 2, gx = xt0 + lx - 2;
            float v = 0.f;
            if (lx < 36 && gy >= 0 && gy < 128 && gx >= 0 && gx < 128)
                v = in[(c0 + ic) * NPIX + gy * 128 + gx];
            s_in[ic][ly][lx] = v;
        }
        __syncthreads();

        #pragma unroll 1
        for (int ic = 0; ic < 4; ic++) {
            #pragma unroll 1
            for (int ky = 0; ky < 5; ky++) {
                float bb[12];
                *(float4*)&bb[0] = *(const float4*)&s_in[ic][ty + ky][tx * 8];
                *(float4*)&bb[4] = *(const float4*)&s_in[ic][ty + ky][tx * 8 + 4];
                *(float4*)&bb[8] = *(const float4*)&s_in[ic][ty + ky][tx * 8 + 8];
                #pragma unroll
                for (int kx = 0; kx < 5; kx++) {
                    float a[8];
                    *(float4*)&a[0] = *(const float4*)&s_w[ic][ky * 5 + kx][0];
                    *(float4*)&a[4] = *(const float4*)&s_w[ic][ky * 5 + kx][4];
                    #pragma unroll
                    for (int j = 0; j < 8; j++)
                        #pragma unroll
                        for (int p = 0; p < 8; p++)
                            acc[j][p] += a[j] * bb[kx + p];
                }
            }
        }
        __syncthreads();
    }

    int pix = (yt0 + ty) * 128 + xt0 + tx * 8;
    float* op = g_f1p[csplit];
    #pragma unroll
    for (int j = 0; j < 8; j++) {
        float* o = &op[(b * 32 + oc0 + j) * NPIX + pix];
        *(float4*)&o[0] = *(float4*)&acc[j][0];
        *(float4*)&o[4] = *(float4*)&acc[j][4];
    }
}

// f1 combine: sum partials + both biases, leaky -> g_f1
__global__ void f1comb_k(const float* __restrict__ bi, const float* __restrict__ bh, int first)
{
    int idx = blockIdx.x * 256 + threadIdx.x;       // over 2*32*NPIX
    int c = (idx >> 14) & 31;
    float v = g_f1p[0][idx] + g_f1p[1][idx];
    if (!first) v += g_f1p[2][idx] + g_f1p[3][idx];
    v += bi[c] + bh[c];
    g_f1[idx] = leaky_f(v);
}

// ---------------------------------------------------------------------------
// flow: conv 5x5 pad 2, 32 -> 26 (padded to 32 oc), 2 channel-half partials.
// grid (8, 8, 2): blockIdx.y = csplit*4 + ocg
// ---------------------------------------------------------------------------
__global__ __launch_bounds__(256) void flow_k(const float* __restrict__ w)
{
    __shared__ __align__(16) float s_in[4][68][40];
    __shared__ __align__(16) float s_w [4][25][8];

    int csplit = blockIdx.y >> 2;                  // 0..1
    int oc0    = (blockIdx.y & 3) * 8;             // 0,8,16,24
    int cbase  = csplit * 16;

    int tid = threadIdx.x;
    int tx = tid & 3, ty = tid >> 2;
    int xt0 = (blockIdx.x & 3) * 32;
    int yt0 = (blockIdx.x >> 2) * 64;
    int b   = blockIdx.z;
    const float* in = g_f1 + (b * 32 + cbase) * NPIX;

    float acc[8][8];
    #pragma unroll
    for (int j = 0; j < 8; j++)
        #pragma unroll
        for (int p = 0; p < 8; p++) acc[j][p] = 0.f;

    for (int c0 = 0; c0 < 16; c0 += 4) {
        for (int i = tid; i < 800; i += 256) {
            int ic = i / 200, r = i % 200, k = r >> 3, j = r & 7;
            s_w[ic][k][j] = (oc0 + j < 26)
                ? w[((oc0 + j) * 32 + cbase + c0 + ic) * 25 + k] : 0.f;
        }
        for (int i = tid; i < 4 * 68 * 40; i += 256) {
            int ic = i / 2720, r = i % 2720, ly = r / 40, lx = r % 40;
            int gy = yt0 + ly - 2, gx = xt0 + lx - 2;
            float v = 0.f;
            if (lx < 36 && gy >= 0 && gy < 128 && gx >= 0 && gx < 128)
                v = in[(c0 + ic) * NPIX + gy * 128 + gx];
            s_in[ic][ly][lx] = v;
        }
        __syncthreads();

        #pragma unroll 1
        for (int ic = 0; ic < 4; ic++) {
            #pragma unroll 1
            for (int ky = 0; ky < 5; ky++) {
                float bb[12];
                *(float4*)&bb[0] = *(const float4*)&s_in[ic][ty + ky][tx * 8];
                *(float4*)&bb[4] = *(const float4*)&s_in[ic][ty + ky][tx * 8 + 4];
                *(float4*)&bb[8] = *(const float4*)&s_in[ic][ty + ky][tx * 8 + 8];
                #pragma unroll
                for (int kx = 0; kx < 5; kx++) {
                    float a[8];
                    *(float4*)&a[0] = *(const float4*)&s_w[ic][ky * 5 + kx][0];
                    *(float4*)&a[4] = *(const float4*)&s_w[ic][ky * 5 + kx][4];
                    #pragma unroll
                    for (int j = 0; j < 8; j++)
                        #pragma unroll
                        for (int p = 0; p < 8; p++)
                            acc[j][p] += a[j] * bb[kx + p];
                }
            }
        }
        __syncthreads();
    }

    int pix = (yt0 + ty) * 128 + xt0 + tx * 8;
    float* op = g_flp[csplit];
    #pragma unroll
    for (int j = 0; j < 8; j++) {
        float* o = &op[(b * 32 + oc0 + j) * NPIX + pix];
        *(float4*)&o[0] = *(float4*)&acc[j][0];
        *(float4*)&o[4] = *(float4*)&acc[j][4];
    }
}

// flow combine: sum 2 partials + bias -> g_fl (26 channels)
__global__ void flowcomb_k(const float* __restrict__ bias)
{
    int idx = blockIdx.x * 256 + threadIdx.x;       // over 2*26*NPIX
    if (idx >= 2 * 26 * NPIX) return;
    int b = idx / (26 * NPIX);
    int r = idx - b * (26 * NPIX);
    int c = r >> 14;
    int pix = r & (NPIX - 1);
    int pi = (b * 32 + c) * NPIX + pix;
    g_fl[idx] = g_flp[0][pi] + g_flp[1][pi] + bias[c];
}

// ---------------------------------------------------------------------------
// warp: bilinear sample hprev at (x-u, y-v), 13 flows x 64 ch.
// ---------------------------------------------------------------------------
__global__ void warp_k(int t, const float* __restrict__ outp)
{
    int pix = blockIdx.x * 256 + threadIdx.x;
    int l   = blockIdx.y;
    int b   = blockIdx.z;

    float u = g_fl[(b * 26 + 2 * l + 0) * NPIX + pix];
    float v = g_fl[(b * 26 + 2 * l + 1) * NPIX + pix];
    float sx = (float)(pix & 127) - u;
    float sy = (float)(pix >> 7)  - v;

    float fx = floorf(sx), fy = floorf(sy);
    float wx1 = sx - fx, wx0 = 1.f - wx1;
    float wy1 = sy - fy, wy0 = 1.f - wy1;
    int x0 = (int)fx, y0 = (int)fy;
    int x1 = x0 + 1,  y1 = y0 + 1;

    bool vx0 = (x0 >= 0) & (x0 <= 127);
    bool vx1 = (x1 >= 0) & (x1 <= 127);
    bool vy0 = (y0 >= 0) & (y0 <= 127);
    bool vy1 = (y1 >= 0) & (y1 <= 127);

    int cx0 = min(max(x0, 0), 127), cx1 = min(max(x1, 0), 127);
    int cy0 = min(max(y0, 0), 127), cy1 = min(max(y1, 0), 127);

    int i00 = cy0 * 128 + cx0, i10 = cy0 * 128 + cx1;
    int i01 = cy1 * 128 + cx0, i11 = cy1 * 128 + cx1;

    float w00 = (vx0 && vy0) ? wx0 * wy0 : 0.f;
    float w10 = (vx1 && vy0) ? wx1 * wy0 : 0.f;
    float w01 = (vx0 && vy1) ? wx0 * wy1 : 0.f;
    float w11 = (vx1 && vy1) ? wx1 * wy1 : 0.f;

    const float* hp = outp + ((b * 6 + (t - 1)) * 64) * NPIX;
    float* wp = g_wp + ((b * 13 + l) * 64) * NPIX + pix;

    #pragma unroll 4
    for (int c = 0; c < 64; c++) {
        const float* hc = hp + c * NPIX;
        float val = w00 * __ldg(&hc[i00]) + w10 * __ldg(&hc[i10])
                  + w01 * __ldg(&hc[i01]) + w11 * __ldg(&hc[i11]);
        wp[c * NPIX] = val;
    }
}

// ---------------------------------------------------------------------------
// ret: SGEMM C[192,16384] = W[192,832] * X[832,16384] + bias, per batch.
// BM=64, BN=256, BK=16, 256 threads, 4x16 spread microtile. grid (64,3,2).
// ---------------------------------------------------------------------------
__global__ __launch_bounds__(256) void ret_k(const float* __restrict__ W,
                                             const float* __restrict__ bias, int first)
{
    __shared__ __align__(16) float As[16][68];
    __shared__ __align__(16) float Bs[16][256];

    int tid = threadIdx.x;
    int b  = blockIdx.z;
    int n0 = blockIdx.x * 256;
    int m0 = blockIdx.y * 64;
    int tm = tid >> 4, tn = tid & 15;
    const float* X = g_wp + b * 832 * NPIX;

    float acc[4][16];
    #pragma unroll
    for (int i = 0; i < 4; i++)
        #pragma unroll
        for (int c = 0; c < 16; c++) acc[i][c] = 0.f;

    int nk = first ? 0 : 52;
    for (int kt = 0; kt < nk; kt++) {
        int k0 = kt * 16;
        #pragma unroll
        for (int r = 0; r < 4; r++) {
            int i = tid + r * 256;
            int m = i >> 4, k = i & 15;
            As[k][m] = W[(m0 + m) * 832 + k0 + k];
        }
        #pragma unroll
        for (int r = 0; r < 4; r++) {
            int fi = tid + r * 256;
            int kb = fi >> 6, nf = fi & 63;
            *(float4*)&Bs[kb][nf * 4] = *(const float4*)&X[(k0 + kb) * NPIX + n0 + nf * 4];
        }
        __syncthreads();

        #pragma unroll
        for (int kk = 0; kk < 16; kk++) {
            float a[4];
            *(float4*)&a[0] = *(const float4*)&As[kk][tm * 4];
            #pragma unroll
            for (int g = 0; g < 4; g++) {
                float4 bv = *(const float4*)&Bs[kk][g * 64 + tn * 4];
                #pragma unroll
                for (int i = 0; i < 4; i++) {
                    acc[i][g * 4 + 0] += a[i] * bv.x;
                    acc[i][g * 4 + 1] += a[i] * bv.y;
                    acc[i][g * 4 + 2] += a[i] * bv.z;
                    acc[i][g * 4 + 3] += a[i] * bv.w;
                }
            }
        }
        __syncthreads();
    }

    float* C = g_h2h + b * 192 * NPIX;
    #pragma unroll
    for (int i = 0; i < 4; i++) {
        int m = m0 + tm * 4 + i;
        float bb = bias[m];
        #pragma unroll
        for (int g = 0; g < 4; g++) {
            float4 o = make_float4(acc[i][g * 4 + 0] + bb, acc[i][g * 4 + 1] + bb,
                                   acc[i][g * 4 + 2] + bb, acc[i][g * 4 + 3] + bb);
            *(float4*)&C[m * NPIX + n0 + g * 64 + tn * 4] = o;
        }
    }
}

// ---------------------------------------------------------------------------
// GRU elementwise update; writes out[b, t].
// ---------------------------------------------------------------------------
__global__ void gru_k(int t, int first, float* __restrict__ outp)
{
    int pix = blockIdx.x * 256 + threadIdx.x;
    int c   = blockIdx.y;
    int b   = blockIdx.z;
    int base = b * 192 * NPIX;

    float ir = g_i2h[base + (c      ) * NPIX + pix];
    float iu = g_i2h[base + (c +  64) * NPIX + pix];
    float im = g_i2h[base + (c + 128) * NPIX + pix];
    float hr = g_h2h[base + (c      ) * NPIX + pix];
    float hu = g_h2h[base + (c +  64) * NPIX + pix];
    float hm = g_h2h[base + (c + 128) * NPIX + pix];

    float r = 1.f / (1.f + expf(-(ir + hr)));
    float z = 1.f / (1.f + expf(-(iu + hu)));
    float m = leaky_f(im + r * hm);

    float hp = first ? 0.f : outp[((b * 6 + t - 1) * 64 + c) * NPIX + pix];
    outp[((b * 6 + t) * 64 + c) * NPIX + pix] = z * hp + (1.f - z) * m;
}

// ---------------------------------------------------------------------------
// Launch
// ---------------------------------------------------------------------------
extern "C" void kernel_launch(void* const* d_in, const int* in_sizes, int n_in,
                              void* d_out, int out_size)
{
    const float* x      = (const float*)d_in[0];
    const float* w_stem = (const float*)d_in[1];
    const float* b_stem = (const float*)d_in[2];
    const float* w_i2h  = (const float*)d_in[3];
    const float* b_i2h  = (const float*)d_in[4];
    const float* w_i2f  = (const float*)d_in[5];
    const float* b_i2f  = (const float*)d_in[6];
    const float* w_h2f  = (const float*)d_in[7];
    const float* b_h2f  = (const float*)d_in[8];
    const float* w_flow = (const float*)d_in[9];
    const float* b_flow = (const float*)d_in[10];
    const float* w_ret  = (const float*)d_in[11];
    const float* b_ret  = (const float*)d_in[12];
    float* outp = (float*)d_out;

    stem_k<<<dim3(64, 96, 2), 256>>>(x, w_stem, b_stem);

    for (int t = 0; t < 6; t++) {
        int first = (t == 0) ? 1 : 0;
        i2h_k   <<<dim3(8, 24, 2), 256>>>(t, w_i2h, b_i2h);
        f1_k    <<<dim3(8, 16, 2), 256>>>(t, first, w_i2f, w_h2f, outp);
        f1comb_k<<<(2 * 32 * NPIX) / 256, 256>>>(b_i2f, b_h2f, first);
        flow_k  <<<dim3(8, 8, 2), 256>>>(w_flow);
        flowcomb_k<<<(2 * 26 * NPIX + 255) / 256, 256>>>(b_flow);
        if (!first)
            warp_k<<<dim3(64, 13, 2), 256>>>(t, outp);
        ret_k   <<<dim3(64, 3, 2), 256>>>(w_ret, b_ret, first);
        gru_k   <<<dim3(64, 64, 2), 256>>>(t, first, outp);
    }
}